// round 12
// baseline (speedup 1.0000x reference)
#include <cuda_runtime.h>
#include <cuda_bf16.h>

typedef unsigned long long u64;
typedef unsigned int u32;
typedef unsigned short u16;

// ============================================================================
// f32x2 packed FMA helpers (phase A)
// ============================================================================
__device__ __forceinline__ u64 fma2(u64 a, u64 b, u64 c) {
    u64 d; asm("fma.rn.f32x2 %0, %1, %2, %3;" : "=l"(d) : "l"(a), "l"(b), "l"(c)); return d;
}
__device__ __forceinline__ u64 pack2(float lo, float hi) {
    u64 r; asm("mov.b64 %0, {%1, %2};" : "=l"(r) : "f"(lo), "f"(hi)); return r;
}
__device__ __forceinline__ void unpack2(u64 a, float& lo, float& hi) {
    asm("mov.b64 {%0, %1}, %2;" : "=f"(lo), "=f"(hi) : "l"(a));
}
union F4U { float4 f; ulonglong2 u; };

__device__ __forceinline__ u32 smem_u32(const void* p) {
    u32 a;
    asm("{ .reg .u64 t; cvta.to.shared.u64 t, %1; cvt.u32.u64 %0, t; }"
        : "=r"(a) : "l"(p));
    return a;
}

// ============================================================================
// mma.sync / ldmatrix helpers (baseline PTX — compiles for compute_103)
// ============================================================================
__device__ __forceinline__ void ldsm4(u32* r, u32 a) {
    asm volatile("ldmatrix.sync.aligned.m8n8.x4.shared.b16 {%0,%1,%2,%3}, [%4];"
        : "=r"(r[0]), "=r"(r[1]), "=r"(r[2]), "=r"(r[3]) : "r"(a));
}
__device__ __forceinline__ void mma16816(float* c, const u32* a, const u32* b) {
    asm volatile("mma.sync.aligned.m16n8k16.row.col.f32.bf16.bf16.f32 "
        "{%0,%1,%2,%3}, {%4,%5,%6,%7}, {%8,%9}, {%0,%1,%2,%3};"
        : "+f"(c[0]), "+f"(c[1]), "+f"(c[2]), "+f"(c[3])
        : "r"(a[0]), "r"(a[1]), "r"(a[2]), "r"(a[3]), "r"(b[0]), "r"(b[1]));
}

// ============================================================================
// Problem constants
// ============================================================================
#define NBINS  16
#define TAILC  3.0f
#define MINV   0.001f
#define D1     32
#define D2     32
#define DFF    256
#define PPD    49
#define DOUT   1568
#define TB     128
#define NTHR   512

// ---- SMEM layout (bytes) ----
#define ASTRIDE   528
#define SMB_AHI   0                       // 128*528 = 67584
#define SMB_ALO   67584                   //              -> 135168
#define SMB_BHI   135168                  // 64*528 = 33792 (rows 0..63)
#define SMB_BLO   168960                  //              -> 202752
#define PARSTR    58
#define SMB_PAR   202752                  // 128*58*4 = 29696 -> 232448? too big
// NOTE: recompute below — B planes are 64 rows now (pad rows zeroed).
// 135168 + 2*33792 = 202752 ; par 29696 -> 232448 == exactly the 227KB cap+?
// Shrink: B planes only need rows 0..63 but ldsm reads <= row 63. Keep 64 rows,
// overlap par with nothing. 232448 bytes is the sm_103 max dyn smem (227.0 KB).
#define SMEM_BYTES 232448
// phase A scratch overlays the B region (only used before phase B)
#define SMB_X1T   135168                  // 32*36*4  = 4608
#define SMB_H1T   139776                  // 256*36*4 = 36864 (ends 176640)

// ============================================================================
// Phase A: 16-row dense micro-GEMMs (2 threads per output feature)
// ============================================================================
template<int K>
__device__ __forceinline__ void dense_relu_16(
    const float* __restrict__ W, const float* __restrict__ bias,
    const float* __restrict__ srcT, float* __restrict__ dstCol, int j)
{
    u64 acc[8];
#pragma unroll
    for (int i = 0; i < 8; i++) acc[i] = 0ull;
#pragma unroll 4
    for (int k = 0; k < K; k++) {
        float w = W[k * DFF + j];
        u64 wp = pack2(w, w);
        const float4* hp = reinterpret_cast<const float4*>(srcT + k * 36);
#pragma unroll
        for (int q = 0; q < 4; q++) {
            F4U v; v.f = hp[q];
            acc[2 * q]     = fma2(v.u.x, wp, acc[2 * q]);
            acc[2 * q + 1] = fma2(v.u.y, wp, acc[2 * q + 1]);
        }
    }
    float b = bias[j];
#pragma unroll
    for (int q = 0; q < 4; q++) {
        float a0, a1, a2, a3;
        unpack2(acc[2 * q], a0, a1);
        unpack2(acc[2 * q + 1], a2, a3);
        reinterpret_cast<float4*>(dstCol)[q] = make_float4(
            fmaxf(a0 + b, 0.f), fmaxf(a1 + b, 0.f),
            fmaxf(a2 + b, 0.f), fmaxf(a3 + b, 0.f));
    }
}

__device__ __forceinline__ void dense2_split_16(
    const float* __restrict__ W2, const float* __restrict__ b2,
    const float* __restrict__ srcT, char* smem, int row_base, int j)
{
    u64 acc[8];
#pragma unroll
    for (int i = 0; i < 8; i++) acc[i] = 0ull;
#pragma unroll 4
    for (int k = 0; k < DFF; k++) {
        float w = W2[k * DFF + j];
        u64 wp = pack2(w, w);
        const float4* hp = reinterpret_cast<const float4*>(srcT + k * 36);
#pragma unroll
        for (int q = 0; q < 4; q++) {
            F4U v; v.f = hp[q];
            acc[2 * q]     = fma2(v.u.x, wp, acc[2 * q]);
            acc[2 * q + 1] = fma2(v.u.y, wp, acc[2 * q + 1]);
        }
    }
    float b = b2[j];
#pragma unroll
    for (int q = 0; q < 4; q++) {
        float v4[4];
        unpack2(acc[2 * q], v4[0], v4[1]);
        unpack2(acc[2 * q + 1], v4[2], v4[3]);
#pragma unroll
        for (int i = 0; i < 4; i++) {
            float v = fmaxf(v4[i] + b, 0.f);
            __nv_bfloat16 h = __float2bfloat16(v);
            __nv_bfloat16 l = __float2bfloat16(v - __bfloat162float(h));
            int row = row_base + 4 * q + i;
            *reinterpret_cast<u16*>(smem + SMB_AHI + row * ASTRIDE + j * 2) =
                __bfloat16_as_ushort(h);
            *reinterpret_cast<u16*>(smem + SMB_ALO + row * ASTRIDE + j * 2) =
                __bfloat16_as_ushort(l);
        }
    }
}

__device__ __forceinline__ float softplus_(float x) {
    return fmaxf(x, 0.f) + __logf(1.f + __expf(-fabsf(x)));
}

// ============================================================================
// W3 slice -> B planes. FILL=true also zero-writes pad rows (p >= PPD);
// steady state skips them (they stay zero from the prologue).
// ============================================================================
template<bool FILL>
__device__ __forceinline__ void stage_b(
    const float* __restrict__ W3, int d, char* smem, int t, int nthr)
{
    for (int idx = t; idx < 64 * 128; idx += nthr) {
        int p = idx & 63, k2 = idx >> 6;
        u32 off = (u32)(p * ASTRIDE + k2 * 4);
        if (p >= PPD) {
            if (FILL) {
                *reinterpret_cast<u32*>(smem + SMB_BHI + off) = 0u;
                *reinterpret_cast<u32*>(smem + SMB_BLO + off) = 0u;
            }
            continue;
        }
        const float* g0 = W3 + (size_t)d * PPD + p;
        float v0 = g0[(size_t)(2 * k2) * DOUT];
        float v1 = g0[(size_t)(2 * k2 + 1) * DOUT];
        __nv_bfloat16 h0 = __float2bfloat16(v0);
        __nv_bfloat16 h1 = __float2bfloat16(v1);
        __nv_bfloat16 l0 = __float2bfloat16(v0 - __bfloat162float(h0));
        __nv_bfloat16 l1 = __float2bfloat16(v1 - __bfloat162float(h1));
        u32 hw = (u32)__bfloat16_as_ushort(h0) | ((u32)__bfloat16_as_ushort(h1) << 16);
        u32 lw = (u32)__bfloat16_as_ushort(l0) | ((u32)__bfloat16_as_ushort(l1) << 16);
        *reinterpret_cast<u32*>(smem + SMB_BHI + off) = hw;
        *reinterpret_cast<u32*>(smem + SMB_BLO + off) = lw;
    }
}

// ============================================================================
// Main kernel — 512 threads, 16 warps
// ============================================================================
__global__ void __launch_bounds__(NTHR, 1)
rq_fused_mma2(const float* __restrict__ x1, const float* __restrict__ x2,
              const float* __restrict__ W1, const float* __restrict__ b1,
              const float* __restrict__ W2, const float* __restrict__ b2,
              const float* __restrict__ W3, const float* __restrict__ b3,
              float* __restrict__ zOut, float* __restrict__ ldOut)
{
    extern __shared__ char smem[];
    float* smf = reinterpret_cast<float*>(smem);
    const u32 sb = smem_u32(smem);
    const int tid = threadIdx.x;
    const int w = tid >> 5;
    const int lane = tid & 31;
    const size_t row0 = (size_t)blockIdx.x * TB;

    // ===================== Phase A: h2 -> bf16 hi/lo A planes ===============
    float* X1T = smf + SMB_X1T / 4;
    float* H1T = smf + SMB_H1T / 4;
    {
        const int j = tid & 255, half = tid >> 8;
        for (int sub = 0; sub < 4; sub++) {
            const int rb = sub * 32;
            __syncthreads();
            for (int idx = tid; idx < 32 * 32; idx += NTHR) {
                int r = idx >> 5, c = idx & 31;
                X1T[c * 36 + r] = x1[(row0 + rb + r) * D1 + c];
            }
            __syncthreads();
            dense_relu_16<D1>(W1, b1, X1T + half * 16,
                              H1T + j * 36 + half * 16, j);
            __syncthreads();
            dense2_split_16(W2, b2, H1T + half * 16, smem, rb + half * 16, j);
        }
    }
    __syncthreads();

    // prologue: stage B(0) with all 512 threads (also zero pad rows)
    stage_b<true>(W3, 0, smem, tid, NTHR);
    __syncthreads();

    // lane decomposition for mma fragments
    const int mt = w & 7;            // m-tile (16 rows)
    const int ng = w >> 3;           // n-group: 0 -> nt 0..3, 1 -> nt 4..6
    const int g = lane >> 2, tig = lane & 3;
    const int at = lane >> 3, ar = lane & 7;
    const u32 aoff = (u32)((16 * mt + (at & 1) * 8 + ar) * ASTRIDE + ((at >> 1) * 8) * 2);
    const u32 aHiB = sb + SMB_AHI + aoff;
    const u32 aLoB = sb + SMB_ALO + aoff;
    // B ldsm4 pair addressing: matrices {nt,k0},{nt,k1},{nt+1,k0},{nt+1,k1}
    const int brow = ((lane >> 4) * 8 + (lane & 7));
    const int bk   = ((lane >> 3) & 1) * 16;
    const u32 boff0 = (u32)((ng * 32 + brow) * ASTRIDE + bk);
    const u32 boff1 = boff0 + 16 * ASTRIDE;
    const u32 bHi0 = sb + SMB_BHI + boff0, bLo0 = sb + SMB_BLO + boff0;
    const u32 bHi1 = sb + SMB_BHI + boff1, bLo1 = sb + SMB_BLO + boff1;

    float ldacc = 0.f;
    float* par = smf + SMB_PAR / 4;

    for (int d = 0; d < D2; d++) {
        // ---------------- MMA: params(d) = h2 @ W3_d (3-pass bf16) ----------
        float c[4][4];
#pragma unroll
        for (int nt = 0; nt < 4; nt++)
#pragma unroll
            for (int i = 0; i < 4; i++) c[nt][i] = 0.f;

        for (int ks = 0; ks < 16; ks++) {
            u32 ah[4], al[4], bh0[4], bl0[4], bh1[4], bl1[4];
            ldsm4(ah, aHiB + ks * 32);
            ldsm4(al, aLoB + ks * 32);
            ldsm4(bh0, bHi0 + ks * 32);
            ldsm4(bl0, bLo0 + ks * 32);
            ldsm4(bh1, bHi1 + ks * 32);
            ldsm4(bl1, bLo1 + ks * 32);
            mma16816(c[0], ah, bh0);     mma16816(c[0], ah, bl0);     mma16816(c[0], al, bh0);
            mma16816(c[1], ah, bh0 + 2); mma16816(c[1], ah, bl0 + 2); mma16816(c[1], al, bh0 + 2);
            mma16816(c[2], ah, bh1);     mma16816(c[2], ah, bl1);     mma16816(c[2], al, bh1);
            if (ng == 0) {
                mma16816(c[3], ah, bh1 + 2); mma16816(c[3], ah, bl1 + 2); mma16816(c[3], al, bh1 + 2);
            }
        }
        // write params (+bias) to SMEM
        const float* b3d = b3 + d * PPD;
#pragma unroll
        for (int nt_i = 0; nt_i < 4; nt_i++) {
            int nt = ng * 4 + nt_i;
            if (nt >= 7) break;
            int col = nt * 8 + 2 * tig;
            float bb0 = (col < PPD) ? b3d[col] : 0.f;
            float bb1 = (col + 1 < PPD) ? b3d[col + 1] : 0.f;
            int rA = 16 * mt + g;
            *reinterpret_cast<float2*>(par + rA * PARSTR + col) =
                make_float2(c[nt_i][0] + bb0, c[nt_i][1] + bb1);
            *reinterpret_cast<float2*>(par + (rA + 8) * PARSTR + col) =
                make_float2(c[nt_i][2] + bb0, c[nt_i][3] + bb1);
        }
        __syncthreads();

        // -------- spline(d) on warps 0-3 | stage B(d+1) on warps 4-15 -------
        if (tid < TB) {
            const float* pp = par + tid * PARSTR;
            float xv = x2[(row0 + tid) * D2 + d];
            bool inside = (xv >= -TAILC) && (xv <= TAILC);
            float xc = fminf(fmaxf(xv, -TAILC), TAILC);

            // widths: softmax + cumsum with fused bin search (no arrays)
            float mx = pp[0];
#pragma unroll
            for (int i = 1; i < NBINS; i++) mx = fmaxf(mx, pp[i]);
            float S = 0.f;
#pragma unroll
            for (int i = 0; i < NBINS; i++) S += __expf(pp[i] - mx);
            float cs = (1.f - NBINS * MINV) / S;
            float run = 0.f;
            int idx = 0; float xk = -TAILC, xk1 = TAILC; bool found = false;
#pragma unroll
            for (int i = 0; i < NBINS; i++) {
                run += MINV + cs * __expf(pp[i] - mx);
                float nxt = fmaf(2.f * TAILC, run, -TAILC);
                if (i < NBINS - 1) {
                    if (nxt <= xc) { idx++; xk = nxt; }
                    else if (!found) { xk1 = nxt; found = true; }
                } else if (!found) xk1 = nxt;
            }
            // heights: softmax + cumsum, capture knots idx / idx+1
            float mx2 = pp[NBINS];
#pragma unroll
            for (int i = 1; i < NBINS; i++) mx2 = fmaxf(mx2, pp[NBINS + i]);
            float S2 = 0.f;
#pragma unroll
            for (int i = 0; i < NBINS; i++) S2 += __expf(pp[NBINS + i] - mx2);
            float cs2 = (1.f - NBINS * MINV) / S2;
            float run2 = 0.f;
            float yk = -TAILC, yk1 = TAILC;
#pragma unroll
            for (int i = 0; i < NBINS; i++) {
                run2 += MINV + cs2 * __expf(pp[NBINS + i] - mx2);
                float nxt = fmaf(2.f * TAILC, run2, -TAILC);
                if (i == idx - 1) yk = nxt;
                if (i == idx)     yk1 = nxt;
            }

            float d0  = MINV + softplus_(pp[2 * NBINS + idx]);
            float d1v = MINV + softplus_(pp[2 * NBINS + idx + 1]);
            float xd = xk1 - xk, yd = yk1 - yk;
            float s  = yd / xd;
            float xi = (xc - xk) / xd;
            float om = 1.f - xi;
            float xim = xi * om;
            float alpha = yd * (s * xi * xi + d0 * xim);
            float beta  = s + (d1v + d0 - 2.f * s) * xim;
            float z  = yk + alpha / beta;
            float dn = s * s * (d1v * xi * xi + 2.f * s * xim + d0 * om * om);
            float ld = __logf(dn) - 2.f * __logf(beta);

            zOut[(row0 + tid) * D2 + d] = inside ? z : xv;
            ldacc += inside ? ld : 0.f;
        } else if (d + 1 < D2) {
            stage_b<false>(W3, d + 1, smem, tid - TB, NTHR - TB);
        }
        __syncthreads();
    }

    if (tid < TB) ldOut[row0 + tid] = ldacc;
}

extern "C" void kernel_launch(void* const* d_in, const int* in_sizes, int n_in,
                              void* d_out, int out_size)
{
    const float* x1 = (const float*)d_in[0];
    const float* x2 = (const float*)d_in[1];
    const float* W1 = (const float*)d_in[2];
    const float* b1 = (const float*)d_in[3];
    const float* W2 = (const float*)d_in[4];
    const float* b2 = (const float*)d_in[5];
    const float* W3 = (const float*)d_in[6];
    const float* b3 = (const float*)d_in[7];

    const int B = in_sizes[0] / D1;
    float* zOut  = (float*)d_out;
    float* ldOut = zOut + (size_t)B * D2;

    cudaFuncSetAttribute(rq_fused_mma2,
                         cudaFuncAttributeMaxDynamicSharedMemorySize, SMEM_BYTES);

    rq_fused_mma2<<<B / TB, NTHR, SMEM_BYTES>>>(x1, x2, W1, b1, W2, b2, W3, b3,
                                                zOut, ldOut);
}

// round 13
// speedup vs baseline: 1.0017x; 1.0017x over previous
#include <cuda_runtime.h>
#include <cuda_bf16.h>

typedef unsigned long long u64;
typedef unsigned int u32;
typedef unsigned short u16;

// ============================================================================
// f32x2 packed FMA helpers (phase A)
// ============================================================================
__device__ __forceinline__ u64 fma2(u64 a, u64 b, u64 c) {
    u64 d; asm("fma.rn.f32x2 %0, %1, %2, %3;" : "=l"(d) : "l"(a), "l"(b), "l"(c)); return d;
}
__device__ __forceinline__ u64 pack2(float lo, float hi) {
    u64 r; asm("mov.b64 %0, {%1, %2};" : "=l"(r) : "f"(lo), "f"(hi)); return r;
}
__device__ __forceinline__ void unpack2(u64 a, float& lo, float& hi) {
    asm("mov.b64 {%0, %1}, %2;" : "=f"(lo), "=f"(hi) : "l"(a));
}
union F4U { float4 f; ulonglong2 u; };

__device__ __forceinline__ u32 smem_u32(const void* p) {
    u32 a;
    asm("{ .reg .u64 t; cvta.to.shared.u64 t, %1; cvt.u32.u64 %0, t; }"
        : "=r"(a) : "l"(p));
    return a;
}

// ============================================================================
// mma.sync / ldmatrix helpers (baseline PTX — compiles for compute_103)
// ============================================================================
__device__ __forceinline__ void ldsm4(u32* r, u32 a) {
    asm volatile("ldmatrix.sync.aligned.m8n8.x4.shared.b16 {%0,%1,%2,%3}, [%4];"
        : "=r"(r[0]), "=r"(r[1]), "=r"(r[2]), "=r"(r[3]) : "r"(a));
}
__device__ __forceinline__ void mma16816(float* c, const u32* a, const u32* b) {
    asm volatile("mma.sync.aligned.m16n8k16.row.col.f32.bf16.bf16.f32 "
        "{%0,%1,%2,%3}, {%4,%5,%6,%7}, {%8,%9}, {%0,%1,%2,%3};"
        : "+f"(c[0]), "+f"(c[1]), "+f"(c[2]), "+f"(c[3])
        : "r"(a[0]), "r"(a[1]), "r"(a[2]), "r"(a[3]), "r"(b[0]), "r"(b[1]));
}

// ============================================================================
// Problem constants
// ============================================================================
#define NBINS  16
#define TAILC  3.0f
#define MINV   0.001f
#define D1     32
#define D2     32
#define DFF    256
#define PPD    49
#define DOUT   1568
#define TB     128
#define NTHR   512

// ---- SMEM layout (bytes) ----
#define ASTRIDE   528
#define SMB_AHI   0                       // 128*528 = 67584
#define SMB_ALO   67584                   //              -> 135168
#define SMB_BHI   135168                  // 64*528 = 33792 (rows 0..63)
#define SMB_BLO   168960                  //              -> 202752
#define PARSTR    58
#define SMB_PAR   202752                  // 128*58*4 = 29696 -> 232448? too big
// NOTE: recompute below — B planes are 64 rows now (pad rows zeroed).
// 135168 + 2*33792 = 202752 ; par 29696 -> 232448 == exactly the 227KB cap+?
// Shrink: B planes only need rows 0..63 but ldsm reads <= row 63. Keep 64 rows,
// overlap par with nothing. 232448 bytes is the sm_103 max dyn smem (227.0 KB).
#define SMEM_BYTES 232448
// phase A scratch overlays the B region (only used before phase B)
#define SMB_X1T   135168                  // 32*36*4  = 4608
#define SMB_H1T   139776                  // 256*36*4 = 36864 (ends 176640)

// ============================================================================
// Phase A: 16-row dense micro-GEMMs (2 threads per output feature)
// ============================================================================
template<int K>
__device__ __forceinline__ void dense_relu_16(
    const float* __restrict__ W, const float* __restrict__ bias,
    const float* __restrict__ srcT, float* __restrict__ dstCol, int j)
{
    u64 acc[8];
#pragma unroll
    for (int i = 0; i < 8; i++) acc[i] = 0ull;
#pragma unroll 4
    for (int k = 0; k < K; k++) {
        float w = W[k * DFF + j];
        u64 wp = pack2(w, w);
        const float4* hp = reinterpret_cast<const float4*>(srcT + k * 36);
#pragma unroll
        for (int q = 0; q < 4; q++) {
            F4U v; v.f = hp[q];
            acc[2 * q]     = fma2(v.u.x, wp, acc[2 * q]);
            acc[2 * q + 1] = fma2(v.u.y, wp, acc[2 * q + 1]);
        }
    }
    float b = bias[j];
#pragma unroll
    for (int q = 0; q < 4; q++) {
        float a0, a1, a2, a3;
        unpack2(acc[2 * q], a0, a1);
        unpack2(acc[2 * q + 1], a2, a3);
        reinterpret_cast<float4*>(dstCol)[q] = make_float4(
            fmaxf(a0 + b, 0.f), fmaxf(a1 + b, 0.f),
            fmaxf(a2 + b, 0.f), fmaxf(a3 + b, 0.f));
    }
}

__device__ __forceinline__ void dense2_split_16(
    const float* __restrict__ W2, const float* __restrict__ b2,
    const float* __restrict__ srcT, char* smem, int row_base, int j)
{
    u64 acc[8];
#pragma unroll
    for (int i = 0; i < 8; i++) acc[i] = 0ull;
#pragma unroll 4
    for (int k = 0; k < DFF; k++) {
        float w = W2[k * DFF + j];
        u64 wp = pack2(w, w);
        const float4* hp = reinterpret_cast<const float4*>(srcT + k * 36);
#pragma unroll
        for (int q = 0; q < 4; q++) {
            F4U v; v.f = hp[q];
            acc[2 * q]     = fma2(v.u.x, wp, acc[2 * q]);
            acc[2 * q + 1] = fma2(v.u.y, wp, acc[2 * q + 1]);
        }
    }
    float b = b2[j];
#pragma unroll
    for (int q = 0; q < 4; q++) {
        float v4[4];
        unpack2(acc[2 * q], v4[0], v4[1]);
        unpack2(acc[2 * q + 1], v4[2], v4[3]);
#pragma unroll
        for (int i = 0; i < 4; i++) {
            float v = fmaxf(v4[i] + b, 0.f);
            __nv_bfloat16 h = __float2bfloat16(v);
            __nv_bfloat16 l = __float2bfloat16(v - __bfloat162float(h));
            int row = row_base + 4 * q + i;
            *reinterpret_cast<u16*>(smem + SMB_AHI + row * ASTRIDE + j * 2) =
                __bfloat16_as_ushort(h);
            *reinterpret_cast<u16*>(smem + SMB_ALO + row * ASTRIDE + j * 2) =
                __bfloat16_as_ushort(l);
        }
    }
}

__device__ __forceinline__ float softplus_(float x) {
    return fmaxf(x, 0.f) + __logf(1.f + __expf(-fabsf(x)));
}

// ============================================================================
// W3 slice -> B planes. FILL=true also zero-writes pad rows (p >= PPD);
// steady state skips them (they stay zero from the prologue).
// ============================================================================
template<bool FILL>
__device__ __forceinline__ void stage_b(
    const float* __restrict__ W3, int d, char* smem, int t, int nthr)
{
    for (int idx = t; idx < 64 * 128; idx += nthr) {
        int p = idx & 63, k2 = idx >> 6;
        u32 off = (u32)(p * ASTRIDE + k2 * 4);
        if (p >= PPD) {
            if (FILL) {
                *reinterpret_cast<u32*>(smem + SMB_BHI + off) = 0u;
                *reinterpret_cast<u32*>(smem + SMB_BLO + off) = 0u;
            }
            continue;
        }
        const float* g0 = W3 + (size_t)d * PPD + p;
        float v0 = g0[(size_t)(2 * k2) * DOUT];
        float v1 = g0[(size_t)(2 * k2 + 1) * DOUT];
        __nv_bfloat16 h0 = __float2bfloat16(v0);
        __nv_bfloat16 h1 = __float2bfloat16(v1);
        __nv_bfloat16 l0 = __float2bfloat16(v0 - __bfloat162float(h0));
        __nv_bfloat16 l1 = __float2bfloat16(v1 - __bfloat162float(h1));
        u32 hw = (u32)__bfloat16_as_ushort(h0) | ((u32)__bfloat16_as_ushort(h1) << 16);
        u32 lw = (u32)__bfloat16_as_ushort(l0) | ((u32)__bfloat16_as_ushort(l1) << 16);
        *reinterpret_cast<u32*>(smem + SMB_BHI + off) = hw;
        *reinterpret_cast<u32*>(smem + SMB_BLO + off) = lw;
    }
}

// ============================================================================
// Main kernel — 512 threads, 16 warps
// ============================================================================
__global__ void __launch_bounds__(NTHR, 1)
rq_fused_mma2(const float* __restrict__ x1, const float* __restrict__ x2,
              const float* __restrict__ W1, const float* __restrict__ b1,
              const float* __restrict__ W2, const float* __restrict__ b2,
              const float* __restrict__ W3, const float* __restrict__ b3,
              float* __restrict__ zOut, float* __restrict__ ldOut)
{
    extern __shared__ char smem[];
    float* smf = reinterpret_cast<float*>(smem);
    const u32 sb = smem_u32(smem);
    const int tid = threadIdx.x;
    const int w = tid >> 5;
    const int lane = tid & 31;
    const size_t row0 = (size_t)blockIdx.x * TB;

    // ===================== Phase A: h2 -> bf16 hi/lo A planes ===============
    float* X1T = smf + SMB_X1T / 4;
    float* H1T = smf + SMB_H1T / 4;
    {
        const int j = tid & 255, half = tid >> 8;
        for (int sub = 0; sub < 4; sub++) {
            const int rb = sub * 32;
            __syncthreads();
            for (int idx = tid; idx < 32 * 32; idx += NTHR) {
                int r = idx >> 5, c = idx & 31;
                X1T[c * 36 + r] = x1[(row0 + rb + r) * D1 + c];
            }
            __syncthreads();
            dense_relu_16<D1>(W1, b1, X1T + half * 16,
                              H1T + j * 36 + half * 16, j);
            __syncthreads();
            dense2_split_16(W2, b2, H1T + half * 16, smem, rb + half * 16, j);
        }
    }
    __syncthreads();

    // prologue: stage B(0) with all 512 threads (also zero pad rows)
    stage_b<true>(W3, 0, smem, tid, NTHR);
    __syncthreads();

    // lane decomposition for mma fragments
    const int mt = w & 7;            // m-tile (16 rows)
    const int ng = w >> 3;           // n-group: 0 -> nt 0..3, 1 -> nt 4..6
    const int g = lane >> 2, tig = lane & 3;
    const int at = lane >> 3, ar = lane & 7;
    const u32 aoff = (u32)((16 * mt + (at & 1) * 8 + ar) * ASTRIDE + ((at >> 1) * 8) * 2);
    const u32 aHiB = sb + SMB_AHI + aoff;
    const u32 aLoB = sb + SMB_ALO + aoff;
    // B ldsm4 pair addressing: matrices {nt,k0},{nt,k1},{nt+1,k0},{nt+1,k1}
    const int brow = ((lane >> 4) * 8 + (lane & 7));
    const int bk   = ((lane >> 3) & 1) * 16;
    const u32 boff0 = (u32)((ng * 32 + brow) * ASTRIDE + bk);
    const u32 boff1 = boff0 + 16 * ASTRIDE;
    const u32 bHi0 = sb + SMB_BHI + boff0, bLo0 = sb + SMB_BLO + boff0;
    const u32 bHi1 = sb + SMB_BHI + boff1, bLo1 = sb + SMB_BLO + boff1;

    float ldacc = 0.f;
    float* par = smf + SMB_PAR / 4;

    for (int d = 0; d < D2; d++) {
        // ---------------- MMA: params(d) = h2 @ W3_d (3-pass bf16) ----------
        float c[4][4];
#pragma unroll
        for (int nt = 0; nt < 4; nt++)
#pragma unroll
            for (int i = 0; i < 4; i++) c[nt][i] = 0.f;

        for (int ks = 0; ks < 16; ks++) {
            u32 ah[4], al[4], bh0[4], bl0[4], bh1[4], bl1[4];
            ldsm4(ah, aHiB + ks * 32);
            ldsm4(al, aLoB + ks * 32);
            ldsm4(bh0, bHi0 + ks * 32);
            ldsm4(bl0, bLo0 + ks * 32);
            ldsm4(bh1, bHi1 + ks * 32);
            ldsm4(bl1, bLo1 + ks * 32);
            mma16816(c[0], ah, bh0);     mma16816(c[0], ah, bl0);     mma16816(c[0], al, bh0);
            mma16816(c[1], ah, bh0 + 2); mma16816(c[1], ah, bl0 + 2); mma16816(c[1], al, bh0 + 2);
            mma16816(c[2], ah, bh1);     mma16816(c[2], ah, bl1);     mma16816(c[2], al, bh1);
            if (ng == 0) {
                mma16816(c[3], ah, bh1 + 2); mma16816(c[3], ah, bl1 + 2); mma16816(c[3], al, bh1 + 2);
            }
        }
        // write params (+bias) to SMEM
        const float* b3d = b3 + d * PPD;
#pragma unroll
        for (int nt_i = 0; nt_i < 4; nt_i++) {
            int nt = ng * 4 + nt_i;
            if (nt >= 7) break;
            int col = nt * 8 + 2 * tig;
            float bb0 = (col < PPD) ? b3d[col] : 0.f;
            float bb1 = (col + 1 < PPD) ? b3d[col + 1] : 0.f;
            int rA = 16 * mt + g;
            *reinterpret_cast<float2*>(par + rA * PARSTR + col) =
                make_float2(c[nt_i][0] + bb0, c[nt_i][1] + bb1);
            *reinterpret_cast<float2*>(par + (rA + 8) * PARSTR + col) =
                make_float2(c[nt_i][2] + bb0, c[nt_i][3] + bb1);
        }
        __syncthreads();

        // -------- spline(d) on warps 0-3 | stage B(d+1) on warps 4-15 -------
        if (tid < TB) {
            const float* pp = par + tid * PARSTR;
            float xv = x2[(row0 + tid) * D2 + d];
            bool inside = (xv >= -TAILC) && (xv <= TAILC);
            float xc = fminf(fmaxf(xv, -TAILC), TAILC);

            // widths: softmax + cumsum with fused bin search (no arrays)
            float mx = pp[0];
#pragma unroll
            for (int i = 1; i < NBINS; i++) mx = fmaxf(mx, pp[i]);
            float S = 0.f;
#pragma unroll
            for (int i = 0; i < NBINS; i++) S += __expf(pp[i] - mx);
            float cs = (1.f - NBINS * MINV) / S;
            float run = 0.f;
            int idx = 0; float xk = -TAILC, xk1 = TAILC; bool found = false;
#pragma unroll
            for (int i = 0; i < NBINS; i++) {
                run += MINV + cs * __expf(pp[i] - mx);
                float nxt = fmaf(2.f * TAILC, run, -TAILC);
                if (i < NBINS - 1) {
                    if (nxt <= xc) { idx++; xk = nxt; }
                    else if (!found) { xk1 = nxt; found = true; }
                } else if (!found) xk1 = nxt;
            }
            // heights: softmax + cumsum, capture knots idx / idx+1
            float mx2 = pp[NBINS];
#pragma unroll
            for (int i = 1; i < NBINS; i++) mx2 = fmaxf(mx2, pp[NBINS + i]);
            float S2 = 0.f;
#pragma unroll
            for (int i = 0; i < NBINS; i++) S2 += __expf(pp[NBINS + i] - mx2);
            float cs2 = (1.f - NBINS * MINV) / S2;
            float run2 = 0.f;
            float yk = -TAILC, yk1 = TAILC;
#pragma unroll
            for (int i = 0; i < NBINS; i++) {
                run2 += MINV + cs2 * __expf(pp[NBINS + i] - mx2);
                float nxt = fmaf(2.f * TAILC, run2, -TAILC);
                if (i == idx - 1) yk = nxt;
                if (i == idx)     yk1 = nxt;
            }

            float d0  = MINV + softplus_(pp[2 * NBINS + idx]);
            float d1v = MINV + softplus_(pp[2 * NBINS + idx + 1]);
            float xd = xk1 - xk, yd = yk1 - yk;
            float s  = yd / xd;
            float xi = (xc - xk) / xd;
            float om = 1.f - xi;
            float xim = xi * om;
            float alpha = yd * (s * xi * xi + d0 * xim);
            float beta  = s + (d1v + d0 - 2.f * s) * xim;
            float z  = yk + alpha / beta;
            float dn = s * s * (d1v * xi * xi + 2.f * s * xim + d0 * om * om);
            float ld = __logf(dn) - 2.f * __logf(beta);

            zOut[(row0 + tid) * D2 + d] = inside ? z : xv;
            ldacc += inside ? ld : 0.f;
        } else if (d + 1 < D2) {
            stage_b<false>(W3, d + 1, smem, tid - TB, NTHR - TB);
        }
        __syncthreads();
    }

    if (tid < TB) ldOut[row0 + tid] = ldacc;
}

extern "C" void kernel_launch(void* const* d_in, const int* in_sizes, int n_in,
                              void* d_out, int out_size)
{
    const float* x1 = (const float*)d_in[0];
    const float* x2 = (const float*)d_in[1];
    const float* W1 = (const float*)d_in[2];
    const float* b1 = (const float*)d_in[3];
    const float* W2 = (const float*)d_in[4];
    const float* b2 = (const float*)d_in[5];
    const float* W3 = (const float*)d_in[6];
    const float* b3 = (const float*)d_in[7];

    const int B = in_sizes[0] / D1;
    float* zOut  = (float*)d_out;
    float* ldOut = zOut + (size_t)B * D2;

    cudaFuncSetAttribute(rq_fused_mma2,
                         cudaFuncAttributeMaxDynamicSharedMemorySize, SMEM_BYTES);

    rq_fused_mma2<<<B / TB, NTHR, SMEM_BYTES>>>(x1, x2, W1, b1, W2, b2, W3, b3,
                                                zOut, ldOut);
}

// round 17
// speedup vs baseline: 1.0032x; 1.0016x over previous
#include <cuda_runtime.h>
#include <cuda_bf16.h>

typedef unsigned long long u64;
typedef unsigned int u32;
typedef unsigned short u16;

// ============================================================================
// f32x2 packed FMA helpers (phase A)
// ============================================================================
__device__ __forceinline__ u64 fma2(u64 a, u64 b, u64 c) {
    u64 d; asm("fma.rn.f32x2 %0, %1, %2, %3;" : "=l"(d) : "l"(a), "l"(b), "l"(c)); return d;
}
__device__ __forceinline__ u64 pack2(float lo, float hi) {
    u64 r; asm("mov.b64 %0, {%1, %2};" : "=l"(r) : "f"(lo), "f"(hi)); return r;
}
__device__ __forceinline__ void unpack2(u64 a, float& lo, float& hi) {
    asm("mov.b64 {%0, %1}, %2;" : "=f"(lo), "=f"(hi) : "l"(a));
}
union F4U { float4 f; ulonglong2 u; };

__device__ __forceinline__ u32 smem_u32(const void* p) {
    u32 a;
    asm("{ .reg .u64 t; cvta.to.shared.u64 t, %1; cvt.u32.u64 %0, t; }"
        : "=r"(a) : "l"(p));
    return a;
}

// ============================================================================
// mma.sync / ldmatrix helpers (baseline PTX — compiles for compute_103)
// ============================================================================
__device__ __forceinline__ void ldsm4(u32* r, u32 a) {
    asm volatile("ldmatrix.sync.aligned.m8n8.x4.shared.b16 {%0,%1,%2,%3}, [%4];"
        : "=r"(r[0]), "=r"(r[1]), "=r"(r[2]), "=r"(r[3]) : "r"(a));
}
__device__ __forceinline__ void mma16816(float* c, const u32* a, const u32* b) {
    asm volatile("mma.sync.aligned.m16n8k16.row.col.f32.bf16.bf16.f32 "
        "{%0,%1,%2,%3}, {%4,%5,%6,%7}, {%8,%9}, {%0,%1,%2,%3};"
        : "+f"(c[0]), "+f"(c[1]), "+f"(c[2]), "+f"(c[3])
        : "r"(a[0]), "r"(a[1]), "r"(a[2]), "r"(a[3]), "r"(b[0]), "r"(b[1]));
}

// ============================================================================
// Problem constants
// ============================================================================
#define NBINS  16
#define TAILC  3.0f
#define MINV   0.001f
#define D1     32
#define D2     32
#define DFF    256
#define PPD    49
#define DOUT   1568
#define TB     128
#define NTHR   512

// ---- SMEM layout (bytes) ----
#define ASTRIDE   528
#define SMB_AHI   0                       // 128*528 = 67584
#define SMB_ALO   67584                   //              -> 135168
#define SMB_BHI   135168                  // 64*528 = 33792 (rows 0..63)
#define SMB_BLO   168960                  //              -> 202752
#define PARSTR    58
#define SMB_PAR   202752                  // 128*58*4 = 29696 -> 232448? too big
// NOTE: recompute below — B planes are 64 rows now (pad rows zeroed).
// 135168 + 2*33792 = 202752 ; par 29696 -> 232448 == exactly the 227KB cap+?
// Shrink: B planes only need rows 0..63 but ldsm reads <= row 63. Keep 64 rows,
// overlap par with nothing. 232448 bytes is the sm_103 max dyn smem (227.0 KB).
#define SMEM_BYTES 232448
// phase A scratch overlays the B region (only used before phase B)
#define SMB_X1T   135168                  // 32*36*4  = 4608
#define SMB_H1T   139776                  // 256*36*4 = 36864 (ends 176640)

// ============================================================================
// Phase A: 16-row dense micro-GEMMs (2 threads per output feature)
// ============================================================================
template<int K>
__device__ __forceinline__ void dense_relu_16(
    const float* __restrict__ W, const float* __restrict__ bias,
    const float* __restrict__ srcT, float* __restrict__ dstCol, int j)
{
    u64 acc[8];
#pragma unroll
    for (int i = 0; i < 8; i++) acc[i] = 0ull;
#pragma unroll 4
    for (int k = 0; k < K; k++) {
        float w = W[k * DFF + j];
        u64 wp = pack2(w, w);
        const float4* hp = reinterpret_cast<const float4*>(srcT + k * 36);
#pragma unroll
        for (int q = 0; q < 4; q++) {
            F4U v; v.f = hp[q];
            acc[2 * q]     = fma2(v.u.x, wp, acc[2 * q]);
            acc[2 * q + 1] = fma2(v.u.y, wp, acc[2 * q + 1]);
        }
    }
    float b = bias[j];
#pragma unroll
    for (int q = 0; q < 4; q++) {
        float a0, a1, a2, a3;
        unpack2(acc[2 * q], a0, a1);
        unpack2(acc[2 * q + 1], a2, a3);
        reinterpret_cast<float4*>(dstCol)[q] = make_float4(
            fmaxf(a0 + b, 0.f), fmaxf(a1 + b, 0.f),
            fmaxf(a2 + b, 0.f), fmaxf(a3 + b, 0.f));
    }
}

__device__ __forceinline__ void dense2_split_16(
    const float* __restrict__ W2, const float* __restrict__ b2,
    const float* __restrict__ srcT, char* smem, int row_base, int j)
{
    u64 acc[8];
#pragma unroll
    for (int i = 0; i < 8; i++) acc[i] = 0ull;
#pragma unroll 4
    for (int k = 0; k < DFF; k++) {
        float w = W2[k * DFF + j];
        u64 wp = pack2(w, w);
        const float4* hp = reinterpret_cast<const float4*>(srcT + k * 36);
#pragma unroll
        for (int q = 0; q < 4; q++) {
            F4U v; v.f = hp[q];
            acc[2 * q]     = fma2(v.u.x, wp, acc[2 * q]);
            acc[2 * q + 1] = fma2(v.u.y, wp, acc[2 * q + 1]);
        }
    }
    float b = b2[j];
#pragma unroll
    for (int q = 0; q < 4; q++) {
        float v4[4];
        unpack2(acc[2 * q], v4[0], v4[1]);
        unpack2(acc[2 * q + 1], v4[2], v4[3]);
#pragma unroll
        for (int i = 0; i < 4; i++) {
            float v = fmaxf(v4[i] + b, 0.f);
            __nv_bfloat16 h = __float2bfloat16(v);
            __nv_bfloat16 l = __float2bfloat16(v - __bfloat162float(h));
            int row = row_base + 4 * q + i;
            *reinterpret_cast<u16*>(smem + SMB_AHI + row * ASTRIDE + j * 2) =
                __bfloat16_as_ushort(h);
            *reinterpret_cast<u16*>(smem + SMB_ALO + row * ASTRIDE + j * 2) =
                __bfloat16_as_ushort(l);
        }
    }
}

__device__ __forceinline__ float softplus_(float x) {
    return fmaxf(x, 0.f) + __logf(1.f + __expf(-fabsf(x)));
}

// ============================================================================
// W3 slice -> B planes. FILL=true also zero-writes pad rows (p >= PPD);
// steady state skips them (they stay zero from the prologue).
// ============================================================================
template<bool FILL>
__device__ __forceinline__ void stage_b(
    const float* __restrict__ W3, int d, char* smem, int t, int nthr)
{
    for (int idx = t; idx < 64 * 128; idx += nthr) {
        int p = idx & 63, k2 = idx >> 6;
        u32 off = (u32)(p * ASTRIDE + k2 * 4);
        if (p >= PPD) {
            if (FILL) {
                *reinterpret_cast<u32*>(smem + SMB_BHI + off) = 0u;
                *reinterpret_cast<u32*>(smem + SMB_BLO + off) = 0u;
            }
            continue;
        }
        const float* g0 = W3 + (size_t)d * PPD + p;
        float v0 = g0[(size_t)(2 * k2) * DOUT];
        float v1 = g0[(size_t)(2 * k2 + 1) * DOUT];
        __nv_bfloat16 h0 = __float2bfloat16(v0);
        __nv_bfloat16 h1 = __float2bfloat16(v1);
        __nv_bfloat16 l0 = __float2bfloat16(v0 - __bfloat162float(h0));
        __nv_bfloat16 l1 = __float2bfloat16(v1 - __bfloat162float(h1));
        u32 hw = (u32)__bfloat16_as_ushort(h0) | ((u32)__bfloat16_as_ushort(h1) << 16);
        u32 lw = (u32)__bfloat16_as_ushort(l0) | ((u32)__bfloat16_as_ushort(l1) << 16);
        *reinterpret_cast<u32*>(smem + SMB_BHI + off) = hw;
        *reinterpret_cast<u32*>(smem + SMB_BLO + off) = lw;
    }
}

// ============================================================================
// Main kernel — 512 threads, 16 warps
// ============================================================================
__global__ void __launch_bounds__(NTHR, 1)
rq_fused_mma2(const float* __restrict__ x1, const float* __restrict__ x2,
              const float* __restrict__ W1, const float* __restrict__ b1,
              const float* __restrict__ W2, const float* __restrict__ b2,
              const float* __restrict__ W3, const float* __restrict__ b3,
              float* __restrict__ zOut, float* __restrict__ ldOut)
{
    extern __shared__ char smem[];
    float* smf = reinterpret_cast<float*>(smem);
    const u32 sb = smem_u32(smem);
    const int tid = threadIdx.x;
    const int w = tid >> 5;
    const int lane = tid & 31;
    const size_t row0 = (size_t)blockIdx.x * TB;

    // ===================== Phase A: h2 -> bf16 hi/lo A planes ===============
    float* X1T = smf + SMB_X1T / 4;
    float* H1T = smf + SMB_H1T / 4;
    {
        const int j = tid & 255, half = tid >> 8;
        for (int sub = 0; sub < 4; sub++) {
            const int rb = sub * 32;
            __syncthreads();
            for (int idx = tid; idx < 32 * 32; idx += NTHR) {
                int r = idx >> 5, c = idx & 31;
                X1T[c * 36 + r] = x1[(row0 + rb + r) * D1 + c];
            }
            __syncthreads();
            dense_relu_16<D1>(W1, b1, X1T + half * 16,
                              H1T + j * 36 + half * 16, j);
            __syncthreads();
            dense2_split_16(W2, b2, H1T + half * 16, smem, rb + half * 16, j);
        }
    }
    __syncthreads();

    // prologue: stage B(0) with all 512 threads (also zero pad rows)
    stage_b<true>(W3, 0, smem, tid, NTHR);
    __syncthreads();

    // lane decomposition for mma fragments
    const int mt = w & 7;            // m-tile (16 rows)
    const int ng = w >> 3;           // n-group: 0 -> nt 0..3, 1 -> nt 4..6
    const int g = lane >> 2, tig = lane & 3;
    const int at = lane >> 3, ar = lane & 7;
    const u32 aoff = (u32)((16 * mt + (at & 1) * 8 + ar) * ASTRIDE + ((at >> 1) * 8) * 2);
    const u32 aHiB = sb + SMB_AHI + aoff;
    const u32 aLoB = sb + SMB_ALO + aoff;
    // B ldsm4 pair addressing: matrices {nt,k0},{nt,k1},{nt+1,k0},{nt+1,k1}
    const int brow = ((lane >> 4) * 8 + (lane & 7));
    const int bk   = ((lane >> 3) & 1) * 16;
    const u32 boff0 = (u32)((ng * 32 + brow) * ASTRIDE + bk);
    const u32 boff1 = boff0 + 16 * ASTRIDE;
    const u32 bHi0 = sb + SMB_BHI + boff0, bLo0 = sb + SMB_BLO + boff0;
    const u32 bHi1 = sb + SMB_BHI + boff1, bLo1 = sb + SMB_BLO + boff1;

    float ldacc = 0.f;
    float* par = smf + SMB_PAR / 4;

    for (int d = 0; d < D2; d++) {
        // ---------------- MMA: params(d) = h2 @ W3_d (3-pass bf16) ----------
        float c[4][4];
#pragma unroll
        for (int nt = 0; nt < 4; nt++)
#pragma unroll
            for (int i = 0; i < 4; i++) c[nt][i] = 0.f;

        for (int ks = 0; ks < 16; ks++) {
            u32 ah[4], al[4], bh0[4], bl0[4], bh1[4], bl1[4];
            ldsm4(ah, aHiB + ks * 32);
            ldsm4(al, aLoB + ks * 32);
            ldsm4(bh0, bHi0 + ks * 32);
            ldsm4(bl0, bLo0 + ks * 32);
            ldsm4(bh1, bHi1 + ks * 32);
            ldsm4(bl1, bLo1 + ks * 32);
            mma16816(c[0], ah, bh0);     mma16816(c[0], ah, bl0);     mma16816(c[0], al, bh0);
            mma16816(c[1], ah, bh0 + 2); mma16816(c[1], ah, bl0 + 2); mma16816(c[1], al, bh0 + 2);
            mma16816(c[2], ah, bh1);     mma16816(c[2], ah, bl1);     mma16816(c[2], al, bh1);
            if (ng == 0) {
                mma16816(c[3], ah, bh1 + 2); mma16816(c[3], ah, bl1 + 2); mma16816(c[3], al, bh1 + 2);
            }
        }
        // write params (+bias) to SMEM
        const float* b3d = b3 + d * PPD;
#pragma unroll
        for (int nt_i = 0; nt_i < 4; nt_i++) {
            int nt = ng * 4 + nt_i;
            if (nt >= 7) break;
            int col = nt * 8 + 2 * tig;
            float bb0 = (col < PPD) ? b3d[col] : 0.f;
            float bb1 = (col + 1 < PPD) ? b3d[col + 1] : 0.f;
            int rA = 16 * mt + g;
            *reinterpret_cast<float2*>(par + rA * PARSTR + col) =
                make_float2(c[nt_i][0] + bb0, c[nt_i][1] + bb1);
            *reinterpret_cast<float2*>(par + (rA + 8) * PARSTR + col) =
                make_float2(c[nt_i][2] + bb0, c[nt_i][3] + bb1);
        }
        __syncthreads();

        // -------- spline(d) on warps 0-3 | stage B(d+1) on warps 4-15 -------
        if (tid < TB) {
            const float* pp = par + tid * PARSTR;
            float xv = x2[(row0 + tid) * D2 + d];
            bool inside = (xv >= -TAILC) && (xv <= TAILC);
            float xc = fminf(fmaxf(xv, -TAILC), TAILC);

            // widths: softmax + cumsum with fused bin search (no arrays)
            float mx = pp[0];
#pragma unroll
            for (int i = 1; i < NBINS; i++) mx = fmaxf(mx, pp[i]);
            float S = 0.f;
#pragma unroll
            for (int i = 0; i < NBINS; i++) S += __expf(pp[i] - mx);
            float cs = (1.f - NBINS * MINV) / S;
            float run = 0.f;
            int idx = 0; float xk = -TAILC, xk1 = TAILC; bool found = false;
#pragma unroll
            for (int i = 0; i < NBINS; i++) {
                run += MINV + cs * __expf(pp[i] - mx);
                float nxt = fmaf(2.f * TAILC, run, -TAILC);
                if (i < NBINS - 1) {
                    if (nxt <= xc) { idx++; xk = nxt; }
                    else if (!found) { xk1 = nxt; found = true; }
                } else if (!found) xk1 = nxt;
            }
            // heights: softmax + cumsum, capture knots idx / idx+1
            float mx2 = pp[NBINS];
#pragma unroll
            for (int i = 1; i < NBINS; i++) mx2 = fmaxf(mx2, pp[NBINS + i]);
            float S2 = 0.f;
#pragma unroll
            for (int i = 0; i < NBINS; i++) S2 += __expf(pp[NBINS + i] - mx2);
            float cs2 = (1.f - NBINS * MINV) / S2;
            float run2 = 0.f;
            float yk = -TAILC, yk1 = TAILC;
#pragma unroll
            for (int i = 0; i < NBINS; i++) {
                run2 += MINV + cs2 * __expf(pp[NBINS + i] - mx2);
                float nxt = fmaf(2.f * TAILC, run2, -TAILC);
                if (i == idx - 1) yk = nxt;
                if (i == idx)     yk1 = nxt;
            }

            float d0  = MINV + softplus_(pp[2 * NBINS + idx]);
            float d1v = MINV + softplus_(pp[2 * NBINS + idx + 1]);
            float xd = xk1 - xk, yd = yk1 - yk;
            float s  = yd / xd;
            float xi = (xc - xk) / xd;
            float om = 1.f - xi;
            float xim = xi * om;
            float alpha = yd * (s * xi * xi + d0 * xim);
            float beta  = s + (d1v + d0 - 2.f * s) * xim;
            float z  = yk + alpha / beta;
            float dn = s * s * (d1v * xi * xi + 2.f * s * xim + d0 * om * om);
            float ld = __logf(dn) - 2.f * __logf(beta);

            zOut[(row0 + tid) * D2 + d] = inside ? z : xv;
            ldacc += inside ? ld : 0.f;
        } else if (d + 1 < D2) {
            stage_b<false>(W3, d + 1, smem, tid - TB, NTHR - TB);
        }
        __syncthreads();
    }

    if (tid < TB) ldOut[row0 + tid] = ldacc;
}

extern "C" void kernel_launch(void* const* d_in, const int* in_sizes, int n_in,
                              void* d_out, int out_size)
{
    const float* x1 = (const float*)d_in[0];
    const float* x2 = (const float*)d_in[1];
    const float* W1 = (const float*)d_in[2];
    const float* b1 = (const float*)d_in[3];
    const float* W2 = (const float*)d_in[4];
    const float* b2 = (const float*)d_in[5];
    const float* W3 = (const float*)d_in[6];
    const float* b3 = (const float*)d_in[7];

    const int B = in_sizes[0] / D1;
    float* zOut  = (float*)d_out;
    float* ldOut = zOut + (size_t)B * D2;

    cudaFuncSetAttribute(rq_fused_mma2,
                         cudaFuncAttributeMaxDynamicSharedMemorySize, SMEM_BYTES);

    rq_fused_mma2<<<B / TB, NTHR, SMEM_BYTES>>>(x1, x2, W1, b1, W2, b2, W3, b3,
                                                zOut, ldOut);
}